// round 1
// baseline (speedup 1.0000x reference)
#include <cuda_runtime.h>

#define IMG_H 512
#define IMG_W 512
#define NIMG  16
#define TW    32
#define TH    32
#define RW    42          // TW + 10 halo
#define RH    42          // TH + 10 halo
#define RSTR  44          // padded raw row stride (floats)
#define NPIX  (NIMG * IMG_H * IMG_W)

// Persistent scalar accumulator (no allocations allowed)
__device__ double g_acc;

__global__ void ssim_init_kernel() { g_acc = 0.0; }

__global__ void __launch_bounds__(256) ssim_main_kernel(
    const float* __restrict__ fused,
    const float* __restrict__ imga,
    const float* __restrict__ imgb)
{
    extern __shared__ float smem[];
    float* sF = smem;                       // [RH][RSTR]
    float* sA = smem + RH * RSTR;
    float* sB = smem + 2 * RH * RSTR;
    float* hb = smem + 3 * RH * RSTR;       // [8][RH][TW]

    // Gaussian(11, sigma=1.5), normalized. Compile-time constants so the
    // unrolled taps lower to FFMA-imm (rt_SMSP = 1 on sm_103a).
    constexpr float GW[11] = {
        0.00102838f, 0.00759876f, 0.03600077f, 0.10936069f, 0.21300553f,
        0.26601172f,
        0.21300553f, 0.10936069f, 0.03600077f, 0.00759876f, 0.00102838f};
    const float c1 = 0.0001f;   // 0.01^2
    const float c2 = 0.0009f;   // 0.03^2

    const int tid = threadIdx.x;
    const int gx0 = blockIdx.x * TW - 5;
    const int gy0 = blockIdx.y * TH - 5;
    const size_t base = (size_t)blockIdx.z * (IMG_H * IMG_W);
    const float* fP = fused + base;
    const float* aP = imga + base;
    const float* bP = imgb + base;

    // ---- Stage 0: load raw halo tile, apply (x+1)/2, zero-pad borders ----
    for (int i = tid; i < RH * RW; i += 256) {
        int y = i / RW;
        int x = i - y * RW;
        int gy = gy0 + y, gx = gx0 + x;
        float fv = 0.f, av = 0.f, bv = 0.f;
        if (gy >= 0 && gy < IMG_H && gx >= 0 && gx < IMG_W) {
            int g = gy * IMG_W + gx;
            fv = (fP[g] + 1.f) * 0.5f;
            av = (aP[g] + 1.f) * 0.5f;
            bv = (bP[g] + 1.f) * 0.5f;
        }
        sF[y * RSTR + x] = fv;
        sA[y * RSTR + x] = av;
        sB[y * RSTR + x] = bv;
    }
    __syncthreads();

    // ---- Stage 1: horizontal 11-tap blur of 8 channels into smem ----
    for (int i = tid; i < RH * TW; i += 256) {
        int y = i >> 5;        // TW == 32
        int x = i & 31;
        const float* fr = sF + y * RSTR + x;
        const float* ar = sA + y * RSTR + x;
        const float* br = sB + y * RSTR + x;
        float s0 = 0.f, s1 = 0.f, s2 = 0.f, s3 = 0.f;
        float s4 = 0.f, s5 = 0.f, s6 = 0.f, s7 = 0.f;
#pragma unroll
        for (int k = 0; k < 11; k++) {
            float w  = GW[k];
            float fv = fr[k], av = ar[k], bv = br[k];
            s0 += w * fv;
            s1 += w * av;
            s2 += w * bv;
            s3 += w * (fv * fv);
            s4 += w * (av * av);
            s5 += w * (bv * bv);
            s6 += w * (fv * av);
            s7 += w * (fv * bv);
        }
        hb[0 * RH * TW + i] = s0;
        hb[1 * RH * TW + i] = s1;
        hb[2 * RH * TW + i] = s2;
        hb[3 * RH * TW + i] = s3;
        hb[4 * RH * TW + i] = s4;
        hb[5 * RH * TW + i] = s5;
        hb[6 * RH * TW + i] = s6;
        hb[7 * RH * TW + i] = s7;
    }
    __syncthreads();

    // ---- Stage 2: vertical blur, 4 outputs per thread, sliding rows ----
    const int x = tid & 31;
    const int ybase = (tid >> 5) * 4;   // 8 groups of 4 rows

    float acc[4][8];
#pragma unroll
    for (int j = 0; j < 4; j++)
#pragma unroll
        for (int c = 0; c < 8; c++) acc[j][c] = 0.f;

#pragma unroll
    for (int r = 0; r < 14; r++) {
        float v[8];
#pragma unroll
        for (int c = 0; c < 8; c++)
            v[c] = hb[c * (RH * TW) + (ybase + r) * TW + x];
#pragma unroll
        for (int j = 0; j < 4; j++) {
            int k = r - j;
            if (k >= 0 && k < 11) {
                float w = GW[k];
#pragma unroll
                for (int c = 0; c < 8; c++) acc[j][c] += w * v[c];
            }
        }
    }

    // ---- SSIM per pixel, accumulate ssim_a + ssim_b ----
    float lsum = 0.f;
#pragma unroll
    for (int j = 0; j < 4; j++) {
        float muF = acc[j][0], muA = acc[j][1], muB = acc[j][2];
        float eF2 = acc[j][3], eA2 = acc[j][4], eB2 = acc[j][5];
        float eFA = acc[j][6], eFB = acc[j][7];
        float muF2 = muF * muF;
        float sF2  = eF2 - muF2;
        {   // pair (fused, img_a)
            float mu22 = muA * muA;
            float mu12 = muF * muA;
            float s2v  = eA2 - mu22;
            float s12  = eFA - mu12;
            float num  = (2.f * mu12 + c1) * (2.f * s12 + c2);
            float den  = (muF2 + mu22 + c1) * (sF2 + s2v + c2);
            lsum += __fdividef(num, den);
        }
        {   // pair (fused, img_b)
            float mu22 = muB * muB;
            float mu12 = muF * muB;
            float s2v  = eB2 - mu22;
            float s12  = eFB - mu12;
            float num  = (2.f * mu12 + c1) * (2.f * s12 + c2);
            float den  = (muF2 + mu22 + c1) * (sF2 + s2v + c2);
            lsum += __fdividef(num, den);
        }
    }

    // ---- Block reduction -> global double accumulator ----
#pragma unroll
    for (int o = 16; o > 0; o >>= 1)
        lsum += __shfl_down_sync(0xffffffffu, lsum, o);

    __shared__ float wsum[8];
    if ((tid & 31) == 0) wsum[tid >> 5] = lsum;
    __syncthreads();
    if (tid < 8) {
        float v = wsum[tid];
        v += __shfl_down_sync(0xffu, v, 4);
        v += __shfl_down_sync(0xffu, v, 2);
        v += __shfl_down_sync(0xffu, v, 1);
        if (tid == 0) atomicAdd(&g_acc, (double)v);
    }
}

__global__ void ssim_fin_kernel(float* __restrict__ out)
{
    out[0] = (float)(1.0 - g_acc / (2.0 * (double)NPIX));
}

extern "C" void kernel_launch(void* const* d_in, const int* in_sizes, int n_in,
                              void* d_out, int out_size)
{
    (void)in_sizes; (void)n_in; (void)out_size;
    const float* fused = (const float*)d_in[0];
    const float* imga  = (const float*)d_in[1];
    const float* imgb  = (const float*)d_in[2];

    const size_t smem_bytes = (size_t)(3 * RH * RSTR + 8 * RH * TW) * sizeof(float);
    cudaFuncSetAttribute(ssim_main_kernel,
                         cudaFuncAttributeMaxDynamicSharedMemorySize,
                         (int)smem_bytes);

    ssim_init_kernel<<<1, 1>>>();
    dim3 grid(IMG_W / TW, IMG_H / TH, NIMG);
    ssim_main_kernel<<<grid, 256, smem_bytes>>>(fused, imga, imgb);
    ssim_fin_kernel<<<1, 1>>>((float*)d_out);
}